// round 7
// baseline (speedup 1.0000x reference)
#include <cuda_runtime.h>

// out[b,c,h,w] = (1/256) * sum_{p,o in 0..8} inp[b, p*9+o, h, w] * sec[b, c, h+p-4, w+o-4]
// B=8, C=256, H=W=128.
// Mapping: warp = 32 lanes = 32 staged channels (weight LDS = broadcast).
// Thread: 2 output rows x 16 px x 1 channel, sliding sec window in h.

#define MD 4
#define NTAPS 81
#define HH 128
#define WW 128
#define CC 256

#define TH 16                    // tile rows
#define TW 16                    // tile cols
#define CB 32                    // channels staged per iteration
#define NCB (CC/CB)              // 8
#define NT 256                   // 8 warps: warp w = row-pair, lane = channel

#define WPLANE (TH*TW)           // 256 floats per weight plane
#define WSM_FLOATS (NTAPS*WPLANE)        // 20736
#define SSTR 28                  // sec row stride (24 data + 4)
#define SROWS 24                 // TH + 2*MD
#define SPLANE 676               // 24*28=672 +4 pad -> mod 32 == 4 (conflict-free lane stride)
#define SSM_FLOATS (CB*SPLANE)   // 21632
#define S_OFF WSM_FLOATS
#define SMEM_BYTES ((WSM_FLOATS+SSM_FLOATS)*4)   // 169472

typedef unsigned long long u64;

__device__ __forceinline__ u64 pack2(float a, float b) {
    u64 r; asm("mov.b64 %0,{%1,%2};" : "=l"(r) : "f"(a), "f"(b)); return r;
}
__device__ __forceinline__ void ffma2(u64& acc, u64 a, u64 b) {
    asm("fma.rn.f32x2 %0, %1, %2, %0;" : "+l"(acc) : "l"(a), "l"(b));
}
__device__ __forceinline__ u64 fmul2(u64 a, u64 b) {
    u64 r; asm("mul.rn.f32x2 %0, %1, %2;" : "=l"(r) : "l"(a), "l"(b)); return r;
}
__device__ __forceinline__ void lds_v2u64(u64& x, u64& y, unsigned addr) {
    asm volatile("ld.shared.v2.b64 {%0,%1},[%2];" : "=l"(x), "=l"(y) : "r"(addr));
}
__device__ __forceinline__ float lo32(u64 a) { return __uint_as_float((unsigned)(a & 0xffffffffull)); }
__device__ __forceinline__ float hi32(u64 a) { return __uint_as_float((unsigned)(a >> 32)); }

__global__ void __launch_bounds__(NT, 1)
corr_transpose_kernel(const float* __restrict__ inp,
                      const float* __restrict__ sec,
                      float* __restrict__ out)
{
    extern __shared__ float smem[];
    float* wsm = smem;                  // [81][16 rows][16 px]
    float* ssm = smem + S_OFF;          // [32 ch][24 rows (stride 28), plane 676]

    const int tid  = threadIdx.x;
    const int lane = tid & 31;          // channel within staged block
    const int wy   = tid >> 5;          // warp id 0..7 -> output row pair
    const int gx   = blockIdx.x * TW;
    const int gy   = blockIdx.y * TH;
    const int b    = blockIdx.z;

    // ---- stage all 81 weight planes for this 16x16 tile (once) ----
    for (int idx = tid; idx < NTAPS * TH * (TW / 4); idx += NT) {
        int col4 = idx & 3;
        int row  = (idx >> 2) & 15;
        int d    = idx >> 6;
        float4 v = *(const float4*)(inp + (((size_t)(b * NTAPS + d) * HH + gy + row) * WW + gx + col4 * 4));
        *(float4*)(wsm + d * WPLANE + row * TW + col4 * 4) = v;
    }

    const unsigned smbase = (unsigned)__cvta_generic_to_shared(smem);
    // sec window base for this thread: its channel plane, tile row offset handled per r
    const unsigned sa_base = smbase + (unsigned)((S_OFF + lane * SPLANE + (2 * wy) * SSTR) * 4);
    // weight rows for this warp's two output rows
    const unsigned wa_row0 = smbase + (unsigned)(((2 * wy + 0) * TW) * 4);
    const unsigned wa_row1 = smbase + (unsigned)(((2 * wy + 1) * TW) * 4);
    const u64 scale2 = pack2(1.0f / (float)CC, 1.0f / (float)CC);

    for (int cb = 0; cb < NCB; cb++) {
        __syncthreads();   // previous compute done before restaging

        // ---- stage 32 channels of sec with halo: ch = lane, rows = wy + 8s ----
        {
            const float* gsec = sec + ((size_t)(b * CC + cb * CB + lane) * HH) * WW;
            float* plane = ssm + lane * SPLANE;
            #pragma unroll
            for (int s = 0; s < 3; s++) {
                int row = wy + 8 * s;              // 0..23
                int r = gy + row - MD;
                #pragma unroll
                for (int c4 = 0; c4 < 6; c4++) {
                    int c = gx - MD + 4 * c4;
                    float4 v = make_float4(0.f, 0.f, 0.f, 0.f);
                    if ((unsigned)r < HH) {
                        if (c >= 0 && c <= WW - 4) {
                            v = *(const float4*)(gsec + (size_t)r * WW + c);
                        } else {
                            const float* gr = gsec + (size_t)r * WW;
                            if ((unsigned)(c + 0) < WW) v.x = gr[c + 0];
                            if ((unsigned)(c + 1) < WW) v.y = gr[c + 1];
                            if ((unsigned)(c + 2) < WW) v.z = gr[c + 2];
                            if ((unsigned)(c + 3) < WW) v.w = gr[c + 3];
                        }
                    }
                    *(float4*)(plane + row * SSTR + 4 * c4) = v;
                }
            }
        }
        __syncthreads();

        // ---- compute: 2 rows x 16 px x 1 channel, sliding sec window over 10 rows ----
        u64 acc0[8], acc1[8];
        #pragma unroll
        for (int k = 0; k < 8; k++) { acc0[k] = 0ull; acc1[k] = 0ull; }

        #pragma unroll
        for (int r = 0; r < 10; r++) {
            // window row (2*wy + r) of this lane's channel: 24 floats
            u64 A[12];
            unsigned sa = sa_base + (unsigned)(r * SSTR * 4);
            lds_v2u64(A[0],  A[1],  sa);
            lds_v2u64(A[2],  A[3],  sa + 16u);
            lds_v2u64(A[4],  A[5],  sa + 32u);
            lds_v2u64(A[6],  A[7],  sa + 48u);
            lds_v2u64(A[8],  A[9],  sa + 64u);
            lds_v2u64(A[10], A[11], sa + 80u);
            u64 M[11];
            #pragma unroll
            for (int i = 0; i < 11; i++) M[i] = pack2(hi32(A[i]), lo32(A[i + 1]));

            // y'=0: p = r (valid r<=8)
            if (r <= 8) {
                const int p = r;
                #pragma unroll
                for (int o = 0; o < 9; o++) {
                    u64 wp[8];
                    unsigned wa = wa_row0 + (unsigned)(((p * 9 + o) * WPLANE) * 4);
                    lds_v2u64(wp[0], wp[1], wa);
                    lds_v2u64(wp[2], wp[3], wa + 16u);
                    lds_v2u64(wp[4], wp[5], wa + 32u);
                    lds_v2u64(wp[6], wp[7], wa + 48u);
                    if ((o & 1) == 0) {
                        #pragma unroll
                        for (int k = 0; k < 8; k++) ffma2(acc0[k], wp[k], A[k + (o >> 1)]);
                    } else {
                        #pragma unroll
                        for (int k = 0; k < 8; k++) ffma2(acc0[k], wp[k], M[k + (o >> 1)]);
                    }
                }
            }
            // y'=1: p = r-1 (valid r>=1)
            if (r >= 1) {
                const int p = r - 1;
                #pragma unroll
                for (int o = 0; o < 9; o++) {
                    u64 wp[8];
                    unsigned wa = wa_row1 + (unsigned)(((p * 9 + o) * WPLANE) * 4);
                    lds_v2u64(wp[0], wp[1], wa);
                    lds_v2u64(wp[2], wp[3], wa + 16u);
                    lds_v2u64(wp[4], wp[5], wa + 32u);
                    lds_v2u64(wp[6], wp[7], wa + 48u);
                    if ((o & 1) == 0) {
                        #pragma unroll
                        for (int k = 0; k < 8; k++) ffma2(acc1[k], wp[k], A[k + (o >> 1)]);
                    } else {
                        #pragma unroll
                        for (int k = 0; k < 8; k++) ffma2(acc1[k], wp[k], M[k + (o >> 1)]);
                    }
                }
            }
        }

        // ---- scale and store 2 rows x 16 px of this lane's channel ----
        {
            const int c = cb * CB + lane;
            float* o0 = out + (((size_t)(b * CC + c) * HH + gy + 2 * wy) * WW + gx);
            float* o1 = o0 + WW;
            #pragma unroll
            for (int q = 0; q < 2; q++) {
                u64 r0 = fmul2(acc0[4 * q + 0], scale2);
                u64 r1 = fmul2(acc0[4 * q + 1], scale2);
                u64 r2 = fmul2(acc0[4 * q + 2], scale2);
                u64 r3 = fmul2(acc0[4 * q + 3], scale2);
                *(float4*)(o0 + 8 * q)     = make_float4(lo32(r0), hi32(r0), lo32(r1), hi32(r1));
                *(float4*)(o0 + 8 * q + 4) = make_float4(lo32(r2), hi32(r2), lo32(r3), hi32(r3));
                u64 s0 = fmul2(acc1[4 * q + 0], scale2);
                u64 s1 = fmul2(acc1[4 * q + 1], scale2);
                u64 s2 = fmul2(acc1[4 * q + 2], scale2);
                u64 s3 = fmul2(acc1[4 * q + 3], scale2);
                *(float4*)(o1 + 8 * q)     = make_float4(lo32(s0), hi32(s0), lo32(s1), hi32(s1));
                *(float4*)(o1 + 8 * q + 4) = make_float4(lo32(s2), hi32(s2), lo32(s3), hi32(s3));
            }
        }
    }
}

extern "C" void kernel_launch(void* const* d_in, const int* in_sizes, int n_in,
                              void* d_out, int out_size)
{
    const float* inp = (const float*)d_in[0];   // [B, 81, 128, 128]
    const float* sec = (const float*)d_in[1];   // [B, 256, 128, 128]
    float* out = (float*)d_out;                 // [B, 256, 128, 128]

    const int B = in_sizes[0] / (NTAPS * HH * WW);

    cudaFuncSetAttribute(corr_transpose_kernel,
                         cudaFuncAttributeMaxDynamicSharedMemorySize, SMEM_BYTES);

    dim3 grid(WW / TW, HH / TH, B);   // (8, 8, 8)
    corr_transpose_kernel<<<grid, NT, SMEM_BYTES>>>(inp, sec, out);
}

// round 8
// speedup vs baseline: 1.1816x; 1.1816x over previous
#include <cuda_runtime.h>

// out[b,c,h,w] = (1/256) * sum_{p,o in 0..8} inp[b, p*9+o, h, w] * sec[b, c, h+p-4, w+o-4]
// B=8, C=256, H=W=128.
// R6 tiling (NT=256, 4ch x 8px per thread) + deep software pipelining:
// weights double-buffered across p, sec window double-buffered across (j,p).

#define MD 4
#define NTAPS 81
#define HH 128
#define WW 128
#define CC 256

#define TH 8
#define TW 32
#define CB 32                    // channels staged per iteration
#define NCB (CC/CB)              // 8
#define NCH 4                    // channels per thread
#define NT 256

#define WSTR 36                  // weight plane row stride (144B)
#define WPLANE (TH*WSTR)         // 288 floats
#define WSM_FLOATS (NTAPS*WPLANE)// 23328
#define SSTR 44                  // sec row stride (176B)
#define SPLANE (16*SSTR)         // 704 floats / channel
#define SSM_FLOATS (CB*SPLANE)   // 22528
#define SMEM_BYTES ((WSM_FLOATS+SSM_FLOATS)*4)  // 183424 B

typedef unsigned long long u64;

__device__ __forceinline__ u64 pack2(float a, float b) {
    u64 r; asm("mov.b64 %0,{%1,%2};" : "=l"(r) : "f"(a), "f"(b)); return r;
}
__device__ __forceinline__ void ffma2(u64& acc, u64 a, u64 b) {
    asm("fma.rn.f32x2 %0, %1, %2, %0;" : "+l"(acc) : "l"(a), "l"(b));
}
__device__ __forceinline__ u64 fmul2(u64 a, u64 b) {
    u64 r; asm("mul.rn.f32x2 %0, %1, %2;" : "=l"(r) : "l"(a), "l"(b)); return r;
}
__device__ __forceinline__ float lo32(u64 a) { return __uint_as_float((unsigned)(a & 0xffffffffull)); }
__device__ __forceinline__ float hi32(u64 a) { return __uint_as_float((unsigned)(a >> 32)); }

struct Win { float4 v0, v1, v2, v3; };

__device__ __forceinline__ Win load_win(const float* p) {
    Win w;
    w.v0 = *(const float4*)(p);
    w.v1 = *(const float4*)(p + 4);
    w.v2 = *(const float4*)(p + 8);
    w.v3 = *(const float4*)(p + 12);
    return w;
}

// load 9 taps x 4 pixel-pairs of weights for row p
__device__ __forceinline__ void load_wts(u64 w[9][4], const float* wbase, int p) {
    #pragma unroll
    for (int o = 0; o < 9; o++) {
        const ulonglong2* q = (const ulonglong2*)(wbase + (p * 9 + o) * WPLANE);
        ulonglong2 q0 = q[0];
        ulonglong2 q1 = q[1];
        w[o][0] = q0.x; w[o][1] = q0.y;
        w[o][2] = q1.x; w[o][3] = q1.y;
    }
}

__device__ __forceinline__ void compute_ch(u64* accj, const u64 w[9][4], const Win& win) {
    float f0 = win.v0.x, f1 = win.v0.y, f2 = win.v0.z, f3 = win.v0.w;
    float f4 = win.v1.x, f5 = win.v1.y, f6 = win.v1.z, f7 = win.v1.w;
    float f8 = win.v2.x, f9 = win.v2.y, f10 = win.v2.z, f11 = win.v2.w;
    float f12 = win.v3.x, f13 = win.v3.y, f14 = win.v3.z, f15 = win.v3.w;
    u64 A[8] = { pack2(f0,f1),  pack2(f2,f3),  pack2(f4,f5),  pack2(f6,f7),
                 pack2(f8,f9),  pack2(f10,f11),pack2(f12,f13),pack2(f14,f15) };
    u64 M[7] = { pack2(f1,f2),  pack2(f3,f4),  pack2(f5,f6),  pack2(f7,f8),
                 pack2(f9,f10), pack2(f11,f12),pack2(f13,f14) };
    #pragma unroll
    for (int o = 0; o < 9; o++) {
        if ((o & 1) == 0) {
            #pragma unroll
            for (int k = 0; k < 4; k++) ffma2(accj[k], w[o][k], A[(o >> 1) + k]);
        } else {
            #pragma unroll
            for (int k = 0; k < 4; k++) ffma2(accj[k], w[o][k], M[(o >> 1) + k]);
        }
    }
}

__global__ void __launch_bounds__(NT, 1)
corr_transpose_kernel(const float* __restrict__ inp,
                      const float* __restrict__ sec,
                      float* __restrict__ out)
{
    extern __shared__ float smem[];
    float* wsm = smem;                  // [81][8][36]
    float* ssm = smem + WSM_FLOATS;     // [32 ch][16 rows][44]

    const int tid = threadIdx.x;
    const int tx  = tid & 3;            // pixel col group (8 px each)
    const int ty  = (tid >> 2) & 7;     // pixel row
    const int cs  = tid >> 5;           // channel subgroup 0..7 (4 ch each)
    const int gx  = blockIdx.x * TW;
    const int gy  = blockIdx.y * TH;
    const int b   = blockIdx.z;

    // ---- stage all 81 weight planes (row stride padded to 36) ----
    for (int idx = tid; idx < NTAPS * TH * (TW / 4); idx += NT) {
        int col4 = idx & 7;
        int row  = (idx >> 3) & 7;
        int d    = idx >> 6;
        float4 v = *(const float4*)(inp + (((size_t)(b * NTAPS + d) * HH + gy + row) * WW + gx + col4 * 4));
        *(float4*)(wsm + d * WPLANE + row * WSTR + col4 * 4) = v;
    }

    const float* wbase = wsm + ty * WSTR + 8 * tx;          // + (p*9+o)*WPLANE
    const float* sbase = ssm + (cs * NCH) * SPLANE + ty * SSTR + 8 * tx;  // + j*SPLANE + p*SSTR
    const u64 scale2 = pack2(1.0f / (float)CC, 1.0f / (float)CC);

    for (int cb = 0; cb < NCB; cb++) {
        __syncthreads();   // previous compute done before restaging

        // ---- stage 32 channels of sec with halo: 2 (ch,row) slots per thread ----
        #pragma unroll
        for (int s = 0; s < 2; s++) {
            int slot = tid + s * NT;
            int srow_t = slot & 15;
            int sch    = slot >> 4;
            const float* gsec = sec + ((size_t)(b * CC + cb * CB + sch) * HH) * WW;
            float* plane = ssm + sch * SPLANE;
            int r = gy + srow_t - MD;
            #pragma unroll
            for (int c4 = 0; c4 < 10; c4++) {
                int c = gx - MD + 4 * c4;
                float4 v = make_float4(0.f, 0.f, 0.f, 0.f);
                if ((unsigned)r < HH) {
                    if (c >= 0 && c <= WW - 4) {
                        v = *(const float4*)(gsec + (size_t)r * WW + c);
                    } else {
                        const float* gr = gsec + (size_t)r * WW;
                        if ((unsigned)(c + 0) < WW) v.x = gr[c + 0];
                        if ((unsigned)(c + 1) < WW) v.y = gr[c + 1];
                        if ((unsigned)(c + 2) < WW) v.z = gr[c + 2];
                        if ((unsigned)(c + 3) < WW) v.w = gr[c + 3];
                    }
                }
                *(float4*)(plane + srow_t * SSTR + 4 * c4) = v;
            }
        }
        __syncthreads();

        // ---- compute: fully pipelined 9p x 4ch ----
        u64 acc[NCH][4];
        #pragma unroll
        for (int j = 0; j < NCH; j++)
            #pragma unroll
            for (int k = 0; k < 4; k++) acc[j][k] = 0ull;

        u64 wp[9][4], wn[9][4];
        load_wts(wp, wbase, 0);
        Win cur = load_win(sbase);          // (p=0, j=0)

        #pragma unroll
        for (int p = 0; p < 9; p++) {
            if (p < 8) load_wts(wn, wbase, p + 1);
            #pragma unroll
            for (int j = 0; j < NCH; j++) {
                Win nxt;
                bool have_nxt = true;
                if (j < NCH - 1)      nxt = load_win(sbase + (j + 1) * SPLANE + p * SSTR);
                else if (p < 8)       nxt = load_win(sbase + (p + 1) * SSTR);
                else                  have_nxt = false;
                compute_ch(acc[j], wp, cur);
                if (have_nxt) cur = nxt;
            }
            if (p < 8) {
                #pragma unroll
                for (int o = 0; o < 9; o++)
                    #pragma unroll
                    for (int k = 0; k < 4; k++) wp[o][k] = wn[o][k];
            }
        }

        // ---- store 4 channels x 8 px ----
        #pragma unroll
        for (int j = 0; j < NCH; j++) {
            int c = cb * CB + cs * NCH + j;
            float* optr = out + (((size_t)(b * CC + c) * HH + gy + ty) * WW + gx + 8 * tx);
            u64 r0 = fmul2(acc[j][0], scale2);
            u64 r1 = fmul2(acc[j][1], scale2);
            u64 r2 = fmul2(acc[j][2], scale2);
            u64 r3 = fmul2(acc[j][3], scale2);
            *(float4*)(optr)     = make_float4(lo32(r0), hi32(r0), lo32(r1), hi32(r1));
            *(float4*)(optr + 4) = make_float4(lo32(r2), hi32(r2), lo32(r3), hi32(r3));
        }
    }
}

extern "C" void kernel_launch(void* const* d_in, const int* in_sizes, int n_in,
                              void* d_out, int out_size)
{
    const float* inp = (const float*)d_in[0];   // [B, 81, 128, 128]
    const float* sec = (const float*)d_in[1];   // [B, 256, 128, 128]
    float* out = (float*)d_out;                 // [B, 256, 128, 128]

    const int B = in_sizes[0] / (NTAPS * HH * WW);

    cudaFuncSetAttribute(corr_transpose_kernel,
                         cudaFuncAttributeMaxDynamicSharedMemorySize, SMEM_BYTES);

    dim3 grid(WW / TW, HH / TH, B);   // (4, 16, 8)
    corr_transpose_kernel<<<grid, NT, SMEM_BYTES>>>(inp, sec, out);
}